// round 3
// baseline (speedup 1.0000x reference)
#include <cuda_runtime.h>

// Fixed problem shape (from setup_inputs): B=32, N=64, L=128, D=256
#define B_      32
#define N_      64
#define L_      128
#define D_      256
#define NB_     (B_ * N_)     // 2048
#define MAXLEN_ (N_ * L_)     // 8192

// Output layout (flat concat of the reference tuple, fp32):
//   src_out      [MAXLEN, B, 1]   -> offset 0,                    size MAXLEN*B      = 262144
//   mb_out       [MAXLEN, B, D]   -> offset 262144,               size MAXLEN*B*D    = 67108864
//   hidden       [1, B, D]        -> offset 262144+67108864,      size B*D           = 8192
//   lengths_out  [B]              -> offset ... + 8192,           size B             = 32
#define OFF_MB      ((size_t)MAXLEN_ * B_)
#define OFF_HID     (OFF_MB + (size_t)MAXLEN_ * B_ * D_)
#define OFF_LEN     (OFF_HID + (size_t)B_ * D_)

__device__ int g_off[NB_];   // exclusive prefix of lengths within each batch row
__device__ int g_ltot[B_];   // total valid length per batch item

// ---------------------------------------------------------------------------
// Kernel A: warp-scan offsets per batch row, totals, zero hidden, lengths_out.
// One block, 1024 threads = 32 warps, warp w handles batch b = w.
// ---------------------------------------------------------------------------
__global__ void prep_kernel(const int* __restrict__ lengths, float* __restrict__ out) {
    float* hidden      = out + OFF_HID;
    float* lengths_out = out + OFF_LEN;
    int tid = threadIdx.x;

    // zero the hidden accumulator region (B*D = 8192 floats, 8 per thread)
#pragma unroll
    for (int i = 0; i < (B_ * D_) / 1024; i++)
        hidden[tid + i * 1024] = 0.0f;

    int b    = tid >> 5;
    int lane = tid & 31;
    int carry = 0;
#pragma unroll
    for (int c = 0; c < N_ / 32; c++) {
        int idx = b * N_ + c * 32 + lane;
        int v = lengths[idx];
        int s = v;
#pragma unroll
        for (int o = 1; o < 32; o <<= 1) {
            int t = __shfl_up_sync(0xffffffffu, s, o);
            if (lane >= o) s += t;
        }
        g_off[idx] = carry + (s - v);            // exclusive prefix
        carry += __shfl_sync(0xffffffffu, s, 31); // row running total
    }
    if (lane == 0) {
        g_ltot[b] = carry;
        lengths_out[b] = (float)carry;
    }
}

// ---------------------------------------------------------------------------
// Kernel B: one block per node nb. Reads the node's valid memory_bank rows,
// scatters them to the packed destination, writes src_out (with recover perm),
// and accumulates the mean-pool partial sum (one shared reduce + 4 atomics).
// 256 threads = 4 positions x 64 float4 lanes per iteration.
// ---------------------------------------------------------------------------
__global__ void scatter_kernel(const float* __restrict__ src,
                               const float4* __restrict__ mb,
                               const int* __restrict__ lengths,
                               const int* __restrict__ recover,
                               float* __restrict__ out) {
    int nb  = blockIdx.x;
    int b   = nb >> 6;            // nb / N_
    int len = lengths[nb];
    int off = g_off[nb];
    int rec = recover[nb];

    float*  out_src = out;
    float4* out_mb  = (float4*)(out + OFF_MB);
    float*  hidden  = out + OFF_HID;

    int tid = threadIdx.x;
    int ps  = tid >> 6;           // 0..3  position sub-index
    int dt  = tid & 63;           // float4 lane within a D=256 row

    float4 acc = make_float4(0.f, 0.f, 0.f, 0.f);

    for (int p0 = 0; p0 < len; p0 += 4) {
        int pos = p0 + ps;
        if (pos < len) {
            float4 v = mb[((size_t)pos * NB_ + nb) * (D_ / 4) + dt];
            acc.x += v.x; acc.y += v.y; acc.z += v.z; acc.w += v.w;
            int t = off + pos;
            out_mb[((size_t)t * B_ + b) * (D_ / 4) + dt] = v;
            if (dt == 0)
                out_src[(size_t)t * B_ + b] = src[(size_t)pos * NB_ + rec];
        }
    }

    // reduce acc over the 4 position sub-groups, scale by 1/Ltot, atomically add
    __shared__ float4 sh[256];
    sh[tid] = acc;
    __syncthreads();
    if (ps == 0) {
        float4 a0 = sh[dt];
        float4 a1 = sh[64 + dt];
        float4 a2 = sh[128 + dt];
        float4 a3 = sh[192 + dt];
        int lt = g_ltot[b];
        if (lt > 0) {
            float inv = 1.0f / (float)lt;
            float* h = hidden + (size_t)b * D_ + dt * 4;
            atomicAdd(h + 0, (a0.x + a1.x + a2.x + a3.x) * inv);
            atomicAdd(h + 1, (a0.y + a1.y + a2.y + a3.y) * inv);
            atomicAdd(h + 2, (a0.z + a1.z + a2.z + a3.z) * inv);
            atomicAdd(h + 3, (a0.w + a1.w + a2.w + a3.w) * inv);
        }
    }
}

// ---------------------------------------------------------------------------
// Kernel C: padded-tail fill. For t >= Ltot[b]: mb_out row = 0, src_out = 1.
// Grid: x = MAXLEN/4 position groups, y = B. Blocks fully inside the valid
// region exit immediately.
// ---------------------------------------------------------------------------
__global__ void tail_kernel(float* __restrict__ out) {
    int b    = blockIdx.y;
    int ltot = g_ltot[b];
    int tid  = threadIdx.x;
    int ps   = tid >> 6;
    int dt   = tid & 63;
    int t    = blockIdx.x * 4 + ps;
    if (t < ltot) return;

    float4* out_mb = (float4*)(out + OFF_MB);
    out_mb[((size_t)t * B_ + b) * (D_ / 4) + dt] = make_float4(0.f, 0.f, 0.f, 0.f);
    if (dt == 0)
        out[(size_t)t * B_ + b] = 1.0f;
}

// ---------------------------------------------------------------------------
extern "C" void kernel_launch(void* const* d_in, const int* in_sizes, int n_in,
                              void* d_out, int out_size) {
    const float* src     = (const float*)d_in[0];   // [L, NB, 1]
    const float* mb      = (const float*)d_in[1];   // [L, NB, D]
    const int*   lengths = (const int*)d_in[2];     // [NB]
    const int*   recover = (const int*)d_in[3];     // [NB]
    float* out = (float*)d_out;

    prep_kernel<<<1, 1024>>>(lengths, out);
    scatter_kernel<<<NB_, 256>>>(src, (const float4*)mb, lengths, recover, out);
    tail_kernel<<<dim3(MAXLEN_ / 4, B_), 256>>>(out);
}

// round 4
// speedup vs baseline: 1.1877x; 1.1877x over previous
#include <cuda_runtime.h>

// Fixed problem shape (from setup_inputs): B=32, N=64, L=128, D=256
#define B_      32
#define N_      64
#define L_      128
#define D_      256
#define NB_     (B_ * N_)     // 2048
#define MAXLEN_ (N_ * L_)     // 8192

// Output layout (flat concat of the reference tuple, fp32):
//   src_out      [MAXLEN, B, 1]
//   mb_out       [MAXLEN, B, D]
//   hidden       [1, B, D]
//   lengths_out  [B]
#define OFF_MB      ((size_t)MAXLEN_ * B_)
#define OFF_HID     (OFF_MB + (size_t)MAXLEN_ * B_ * D_)
#define OFF_LEN     (OFF_HID + (size_t)B_ * D_)

// Per-node partial sums for the mean-pool (no atomics, no zero-init needed:
// every block unconditionally writes its own row).
__device__ float4 g_nodesum[NB_ * (D_ / 4)];   // [NB][64] float4 = 2 MB

// ---------------------------------------------------------------------------
// Fused kernel: one block per node nb (2048 blocks x 256 threads).
//  1. warp 0 scans this batch row's 64 lengths -> sh_off[64], sh_ltot
//  2. scatter the node's valid rows (read mb, write packed mb_out + src_out),
//     accumulating the mean-pool partial sum in registers
//  3. write this node's partial sum row to g_nodesum
//  4. write this block's 1/64 share of the batch row's zero tail
// ---------------------------------------------------------------------------
__global__ void __launch_bounds__(256) fused_kernel(
        const float* __restrict__ src,
        const float4* __restrict__ mb,
        const int* __restrict__ lengths,
        const int* __restrict__ recover,
        float* __restrict__ out) {
    __shared__ int sh_off[N_];
    __shared__ int sh_ltot;
    __shared__ float4 sh[256];

    int nb  = blockIdx.x;
    int b   = nb >> 6;            // nb / N_
    int n   = nb & 63;            // node index within batch row
    int tid = threadIdx.x;
    int lane = tid & 31;

    // --- per-row length scan (warp 0, two 32-chunks) ---
    if (tid < 32) {
        int carry = 0;
#pragma unroll
        for (int c = 0; c < 2; c++) {
            int idx = c * 32 + lane;
            int v = lengths[b * N_ + idx];
            int s = v;
#pragma unroll
            for (int o = 1; o < 32; o <<= 1) {
                int t = __shfl_up_sync(0xffffffffu, s, o);
                if (lane >= o) s += t;
            }
            sh_off[idx] = carry + (s - v);
            carry += __shfl_sync(0xffffffffu, s, 31);
        }
        if (lane == 0) sh_ltot = carry;
    }
    __syncthreads();

    int len  = lengths[nb];
    int off  = sh_off[n];
    int ltot = sh_ltot;
    int rec  = recover[nb];

    float*  out_src = out;
    float4* out_mb  = (float4*)(out + OFF_MB);

    int ps = tid >> 6;            // 0..3 position sub-index
    int dt = tid & 63;            // float4 lane within a D=256 row

    // --- valid-region scatter + accumulate ---
    float4 acc = make_float4(0.f, 0.f, 0.f, 0.f);
    for (int p0 = 0; p0 < len; p0 += 4) {
        int pos = p0 + ps;
        if (pos < len) {
            float4 v = __ldcs(&mb[((size_t)pos * NB_ + nb) * (D_ / 4) + dt]);
            acc.x += v.x; acc.y += v.y; acc.z += v.z; acc.w += v.w;
            int t = off + pos;
            __stcs(&out_mb[((size_t)t * B_ + b) * (D_ / 4) + dt], v);
            if (dt == 0)
                out_src[(size_t)t * B_ + b] = src[(size_t)pos * NB_ + rec];
        }
    }

    // --- reduce the 4 position sub-groups, write this node's partial row ---
    sh[tid] = acc;
    __syncthreads();
    if (ps == 0) {
        float4 a0 = sh[dt];
        float4 a1 = sh[64 + dt];
        float4 a2 = sh[128 + dt];
        float4 a3 = sh[192 + dt];
        float4 r;
        r.x = a0.x + a1.x + a2.x + a3.x;
        r.y = a0.y + a1.y + a2.y + a3.y;
        r.z = a0.z + a1.z + a2.z + a3.z;
        r.w = a0.w + a1.w + a2.w + a3.w;
        g_nodesum[(size_t)nb * (D_ / 4) + dt] = r;
    }

    // --- tail fill: this block covers its 1/64 share of rows >= ltot ---
    int tail_cnt = MAXLEN_ - ltot;
    int cs = (tail_cnt + N_ - 1) / N_;               // rows per block
    int t0 = ltot + n * cs;
    int t1 = min(t0 + cs, MAXLEN_);
    const float4 z4 = make_float4(0.f, 0.f, 0.f, 0.f);
    for (int tb = t0; tb < t1; tb += 4) {
        int t = tb + ps;
        if (t < t1) {
            __stcs(&out_mb[((size_t)t * B_ + b) * (D_ / 4) + dt], z4);
            if (dt == 0)
                out_src[(size_t)t * B_ + b] = 1.0f;
        }
    }
}

// ---------------------------------------------------------------------------
// Epilogue: reduce 64 node-partials per batch item -> hidden, write lengths.
// 32 blocks x 256 threads; thread d sums column d over 64 nodes (coalesced).
// ---------------------------------------------------------------------------
__global__ void __launch_bounds__(256) hidden_kernel(
        const int* __restrict__ lengths, float* __restrict__ out) {
    __shared__ int sh_ltot;
    int b   = blockIdx.x;
    int tid = threadIdx.x;

    if (tid == 0) {
        int s = 0;
#pragma unroll
        for (int i = 0; i < N_; i++) s += lengths[b * N_ + i];
        sh_ltot = s;
        out[OFF_LEN + b] = (float)s;
    }
    __syncthreads();
    int lt = sh_ltot;
    float inv = lt > 0 ? 1.0f / (float)lt : 0.0f;

    const float* ns = (const float*)g_nodesum;
    float s = 0.0f;
#pragma unroll 8
    for (int n2 = 0; n2 < N_; n2++)
        s += ns[((size_t)(b * N_ + n2)) * D_ + tid];
    out[OFF_HID + (size_t)b * D_ + tid] = s * inv;
}

// ---------------------------------------------------------------------------
extern "C" void kernel_launch(void* const* d_in, const int* in_sizes, int n_in,
                              void* d_out, int out_size) {
    const float* src     = (const float*)d_in[0];   // [L, NB, 1]
    const float* mb      = (const float*)d_in[1];   // [L, NB, D]
    const int*   lengths = (const int*)d_in[2];     // [NB]
    const int*   recover = (const int*)d_in[3];     // [NB]
    float* out = (float*)d_out;

    fused_kernel<<<NB_, 256>>>(src, (const float4*)mb, lengths, recover, out);
    hidden_kernel<<<B_, 256>>>(lengths, out);
}

// round 6
// speedup vs baseline: 1.2878x; 1.0842x over previous
#include <cuda_runtime.h>

// Fixed problem shape (from setup_inputs): B=32, N=64, L=128, D=256
#define B_      32
#define N_      64
#define L_      128
#define D_      256
#define NB_     (B_ * N_)     // 2048
#define MAXLEN_ (N_ * L_)     // 8192

// Output layout (flat concat of the reference tuple, fp32):
//   src_out      [MAXLEN, B, 1]
//   mb_out       [MAXLEN, B, D]
//   hidden       [1, B, D]
//   lengths_out  [B]
#define OFF_MB      ((size_t)MAXLEN_ * B_)
#define OFF_HID     (OFF_MB + (size_t)MAXLEN_ * B_ * D_)
#define OFF_LEN     (OFF_HID + (size_t)B_ * D_)

// ---------------------------------------------------------------------------
// Init: zero the hidden accumulator region (B*D = 8192 floats). Must run
// before fused_kernel's atomic accumulation (d_out is poisoned to 0xAA).
// ---------------------------------------------------------------------------
__global__ void init_kernel(float* __restrict__ out) {
    int i = blockIdx.x * 1024 + threadIdx.x;
    ((float4*)(out + OFF_HID))[i] = make_float4(0.f, 0.f, 0.f, 0.f);
}

// ---------------------------------------------------------------------------
// Fused kernel: one block per node nb (2048 blocks x 256 threads).
//  1. warp 0 scans this batch row's 64 lengths -> sh_off[64], sh_ltot
//  2. scatter the node's valid rows (read mb, write packed mb_out + src_out),
//     accumulating the mean-pool partial sum in registers (2x unrolled)
//  3. shared-reduce the partial sum, scale by 1/ltot, atomicAdd into hidden
//  4. write this block's 1/64 share of the batch row's zero/one tail
//  (block with n==0 also writes lengths_out[b])
// ---------------------------------------------------------------------------
__global__ void __launch_bounds__(256) fused_kernel(
        const float* __restrict__ src,
        const float4* __restrict__ mb,
        const int* __restrict__ lengths,
        const int* __restrict__ recover,
        float* __restrict__ out) {
    __shared__ int sh_off[N_];
    __shared__ int sh_ltot;
    __shared__ float4 sh[256];

    int nb  = blockIdx.x;
    int b   = nb >> 6;            // nb / N_
    int n   = nb & 63;            // node index within batch row
    int tid = threadIdx.x;
    int lane = tid & 31;

    // --- per-row length scan (warp 0, two 32-chunks) ---
    if (tid < 32) {
        int carry = 0;
#pragma unroll
        for (int c = 0; c < 2; c++) {
            int idx = c * 32 + lane;
            int v = lengths[b * N_ + idx];
            int s = v;
#pragma unroll
            for (int o = 1; o < 32; o <<= 1) {
                int t = __shfl_up_sync(0xffffffffu, s, o);
                if (lane >= o) s += t;
            }
            sh_off[idx] = carry + (s - v);
            carry += __shfl_sync(0xffffffffu, s, 31);
        }
        if (lane == 0) sh_ltot = carry;
    }
    __syncthreads();

    int len  = lengths[nb];
    int off  = sh_off[n];
    int ltot = sh_ltot;
    int rec  = recover[nb];

    if (n == 0 && tid == 0)
        out[OFF_LEN + b] = (float)ltot;

    float*  out_src = out;
    float4* out_mb  = (float4*)(out + OFF_MB);
    float*  hidden  = out + OFF_HID;

    int ps = tid >> 6;            // 0..3 position sub-index
    int dt = tid & 63;            // float4 lane within a D=256 row

    // --- valid-region scatter + accumulate, 2 positions per thread/iter ---
    float4 acc = make_float4(0.f, 0.f, 0.f, 0.f);
    int p0 = 0;
    for (; p0 + 8 <= len; p0 += 8) {
        int posA = p0 + ps;
        int posB = p0 + 4 + ps;
        float4 vA = __ldcs(&mb[((size_t)posA * NB_ + nb) * (D_ / 4) + dt]);
        float4 vB = __ldcs(&mb[((size_t)posB * NB_ + nb) * (D_ / 4) + dt]);
        float sA = 0.f, sB = 0.f;
        if (dt == 0) {
            sA = src[(size_t)posA * NB_ + rec];
            sB = src[(size_t)posB * NB_ + rec];
        }
        acc.x += vA.x + vB.x; acc.y += vA.y + vB.y;
        acc.z += vA.z + vB.z; acc.w += vA.w + vB.w;
        int tA = off + posA, tB = off + posB;
        __stcs(&out_mb[((size_t)tA * B_ + b) * (D_ / 4) + dt], vA);
        __stcs(&out_mb[((size_t)tB * B_ + b) * (D_ / 4) + dt], vB);
        if (dt == 0) {
            out_src[(size_t)tA * B_ + b] = sA;
            out_src[(size_t)tB * B_ + b] = sB;
        }
    }
    for (; p0 < len; p0 += 4) {
        int pos = p0 + ps;
        if (pos < len) {
            float4 v = __ldcs(&mb[((size_t)pos * NB_ + nb) * (D_ / 4) + dt]);
            acc.x += v.x; acc.y += v.y; acc.z += v.z; acc.w += v.w;
            int t = off + pos;
            __stcs(&out_mb[((size_t)t * B_ + b) * (D_ / 4) + dt], v);
            if (dt == 0)
                out_src[(size_t)t * B_ + b] = src[(size_t)pos * NB_ + rec];
        }
    }

    // --- reduce the 4 position sub-groups, atomicAdd scaled row to hidden ---
    sh[tid] = acc;
    __syncthreads();
    if (ps == 0 && ltot > 0) {
        float4 a0 = sh[dt];
        float4 a1 = sh[64 + dt];
        float4 a2 = sh[128 + dt];
        float4 a3 = sh[192 + dt];
        float inv = 1.0f / (float)ltot;
        float* h = hidden + (size_t)b * D_ + dt * 4;
        atomicAdd(h + 0, (a0.x + a1.x + a2.x + a3.x) * inv);
        atomicAdd(h + 1, (a0.y + a1.y + a2.y + a3.y) * inv);
        atomicAdd(h + 2, (a0.z + a1.z + a2.z + a3.z) * inv);
        atomicAdd(h + 3, (a0.w + a1.w + a2.w + a3.w) * inv);
    }

    // --- tail fill: this block covers its 1/64 share of rows >= ltot ---
    int tail_cnt = MAXLEN_ - ltot;
    int cs = (tail_cnt + N_ - 1) / N_;               // rows per block
    int t0 = ltot + n * cs;
    int t1 = min(t0 + cs, MAXLEN_);
    const float4 z4 = make_float4(0.f, 0.f, 0.f, 0.f);
    for (int tb = t0; tb < t1; tb += 4) {
        int t = tb + ps;
        if (t < t1) {
            __stcs(&out_mb[((size_t)t * B_ + b) * (D_ / 4) + dt], z4);
            if (dt == 0)
                out_src[(size_t)t * B_ + b] = 1.0f;
        }
    }
}

// ---------------------------------------------------------------------------
extern "C" void kernel_launch(void* const* d_in, const int* in_sizes, int n_in,
                              void* d_out, int out_size) {
    const float* src     = (const float*)d_in[0];   // [L, NB, 1]
    const float* mb      = (const float*)d_in[1];   // [L, NB, D]
    const int*   lengths = (const int*)d_in[2];     // [NB]
    const int*   recover = (const int*)d_in[3];     // [NB]
    float* out = (float*)d_out;

    init_kernel<<<2, 1024>>>(out);                  // zero hidden region
    fused_kernel<<<NB_, 256>>>(src, (const float4*)mb, lengths, recover, out);
}